// round 2
// baseline (speedup 1.0000x reference)
#include <cuda_runtime.h>
#include <cuda_bf16.h>

#define N_NODES 100000
#define N_EDGES 3200000
#define NFEAT 1433
#define NHID 40
#define NCLASS 7

// ---------------- scratch (device globals; no allocations allowed) -------------
__device__ float g_support1[N_NODES * NHID];   // x @ W1
__device__ float g_agg1[N_NODES * NHID];       // scatter-add target, layer 1
__device__ float g_support2[N_NODES * NCLASS]; // h @ W2

// ---------------- f32x2 helpers (sm_100+ packed fp32) -------------------------
__device__ __forceinline__ unsigned long long pack_f32x2(float x) {
    unsigned long long p;
    asm("mov.b64 %0, {%1, %1};" : "=l"(p) : "f"(x));
    return p;
}
__device__ __forceinline__ void ffma2(unsigned long long& d,
                                      unsigned long long a,
                                      unsigned long long b) {
    asm("fma.rn.f32x2 %0, %1, %2, %0;" : "+l"(d) : "l"(a), "l"(b));
}
__device__ __forceinline__ float2 unpack_f32x2(unsigned long long p) {
    float2 r;
    asm("mov.b64 {%0, %1}, %2;" : "=f"(r.x), "=f"(r.y) : "l"(p));
    return r;
}

// ---------------- GEMM1: support1 = x @ W1  (N x 1433 @ 1433 x 40) ------------
// Block: 128 threads, tile 128 rows x 40 cols. Thread tile: 4 rows x 10 cols,
// accumulated as 4x5 f32x2 pairs via fma.rn.f32x2 (2x FFMA throughput).
#define G1_KC 32
__global__ __launch_bounds__(128) void gemm1_kernel(const float* __restrict__ x,
                                                    const float* __restrict__ W1) {
    __shared__ float sx[128][G1_KC + 1];  // +1 pad: conflict-free row reads
    __shared__ float sw[G1_KC][NHID];

    const int tid = threadIdx.x;
    const int cg = tid & 3;    // col group: 10 cols each
    const int rt = tid >> 2;   // row thread: 4 rows each (0..31)
    const int row0 = blockIdx.x * 128;

    unsigned long long acc[4][5];
#pragma unroll
    for (int i = 0; i < 4; i++)
#pragma unroll
        for (int j = 0; j < 5; j++) acc[i][j] = 0ull;

    for (int kb = 0; kb < NFEAT; kb += G1_KC) {
        // load x tile (coalesced along k)
#pragma unroll
        for (int i = 0; i < 32; i++) {
            int idx = tid + i * 128;
            int r = idx >> 5;
            int kk = idx & 31;
            int gr = row0 + r;
            int gk = kb + kk;
            float v = 0.f;
            if (gr < N_NODES && gk < NFEAT) v = x[gr * NFEAT + gk];
            sx[r][kk] = v;
        }
        // load W tile (32 x 40 = 1280 elems, 10 per thread)
#pragma unroll
        for (int i = 0; i < 10; i++) {
            int idx = tid + i * 128;
            int kk = idx / NHID;
            int c = idx % NHID;
            int gk = kb + kk;
            sw[kk][c] = (gk < NFEAT) ? W1[gk * NHID + c] : 0.f;
        }
        __syncthreads();

#pragma unroll
        for (int kk = 0; kk < G1_KC; kk++) {
            unsigned long long wv[5];
            const float* wrow = &sw[kk][cg * 10];
#pragma unroll
            for (int j = 0; j < 5; j++)
                wv[j] = *reinterpret_cast<const unsigned long long*>(wrow + 2 * j);
#pragma unroll
            for (int i = 0; i < 4; i++) {
                unsigned long long xp = pack_f32x2(sx[rt * 4 + i][kk]);
#pragma unroll
                for (int j = 0; j < 5; j++) ffma2(acc[i][j], xp, wv[j]);
            }
        }
        __syncthreads();
    }

#pragma unroll
    for (int i = 0; i < 4; i++) {
        int gr = row0 + rt * 4 + i;
        if (gr < N_NODES) {
#pragma unroll
            for (int j = 0; j < 5; j++) {
                float2 v = unpack_f32x2(acc[i][j]);
                *reinterpret_cast<float2*>(&g_support1[gr * NHID + cg * 10 + 2 * j]) = v;
            }
        }
    }
}

// ---------------- zero kernels -------------------------------------------------
__global__ void zero_agg1_kernel() {
    int i = blockIdx.x * blockDim.x + threadIdx.x;
    float4* p = reinterpret_cast<float4*>(g_agg1);
    if (i < N_NODES * NHID / 4) p[i] = make_float4(0.f, 0.f, 0.f, 0.f);
}
__global__ void zero_out_kernel(float* __restrict__ out) {
    int i = blockIdx.x * blockDim.x + threadIdx.x;
    if (i < N_NODES * NCLASS) out[i] = 0.f;
}

// ---------------- scatter 1: agg1[dst] += support1[src] * w  (40 wide) ---------
// One warp per edge: lanes 0..31 handle f=lane, lanes 0..7 also f=lane+32.
__global__ __launch_bounds__(256) void scatter1_kernel(const int* __restrict__ src,
                                                       const int* __restrict__ dst,
                                                       const float* __restrict__ ew) {
    int gtid = blockIdx.x * blockDim.x + threadIdx.x;
    int e = gtid >> 5;
    int lane = threadIdx.x & 31;
    if (e >= N_EDGES) return;
    int s = src[e];
    int d = dst[e];
    float w = ew[e];
    const float* srow = g_support1 + s * NHID;
    float* drow = g_agg1 + d * NHID;
    atomicAdd(&drow[lane], srow[lane] * w);
    if (lane < NHID - 32)
        atomicAdd(&drow[32 + lane], srow[32 + lane] * w);
}

// ---------------- layer-1 epilogue fused with GEMM2 ----------------------------
// h = relu(agg1 + b1) * dropout; support2 = h @ W2
__global__ __launch_bounds__(256) void mid_kernel(const float* __restrict__ b1,
                                                  const float* __restrict__ W2,
                                                  const float* __restrict__ mask) {
    __shared__ float sW2[NHID][NCLASS];
    __shared__ float sb1[NHID];
    int tid = threadIdx.x;
    // NHID*NCLASS = 280 > blockDim (256): MUST be a strided loop.
    for (int i = tid; i < NHID * NCLASS; i += blockDim.x)
        sW2[i / NCLASS][i % NCLASS] = W2[i];
    if (tid < NHID) sb1[tid] = b1[tid];
    __syncthreads();

    int n = blockIdx.x * blockDim.x + tid;
    if (n >= N_NODES) return;

    float acc[NCLASS];
#pragma unroll
    for (int c = 0; c < NCLASS; c++) acc[c] = 0.f;

    const float4* arow = reinterpret_cast<const float4*>(g_agg1 + n * NHID);
    const float4* mrow = reinterpret_cast<const float4*>(mask + n * NHID);
#pragma unroll
    for (int q = 0; q < NHID / 4; q++) {
        float4 a = arow[q];
        float4 m = mrow[q];
        float hv[4];
        hv[0] = (m.x > 0.5f) ? fmaxf(a.x + sb1[4 * q + 0], 0.f) * 2.f : 0.f;
        hv[1] = (m.y > 0.5f) ? fmaxf(a.y + sb1[4 * q + 1], 0.f) * 2.f : 0.f;
        hv[2] = (m.z > 0.5f) ? fmaxf(a.z + sb1[4 * q + 2], 0.f) * 2.f : 0.f;
        hv[3] = (m.w > 0.5f) ? fmaxf(a.w + sb1[4 * q + 3], 0.f) * 2.f : 0.f;
#pragma unroll
        for (int u = 0; u < 4; u++) {
#pragma unroll
            for (int c = 0; c < NCLASS; c++) acc[c] += hv[u] * sW2[4 * q + u][c];
        }
    }
#pragma unroll
    for (int c = 0; c < NCLASS; c++) g_support2[n * NCLASS + c] = acc[c];
}

// ---------------- scatter 2: out[dst] += support2[src] * w  (7 wide) -----------
// 8 threads per edge (thread f = tid&7, active for f<7).
__global__ __launch_bounds__(256) void scatter2_kernel(const int* __restrict__ src,
                                                       const int* __restrict__ dst,
                                                       const float* __restrict__ ew,
                                                       float* __restrict__ out) {
    int gtid = blockIdx.x * blockDim.x + threadIdx.x;
    int e = gtid >> 3;
    int f = gtid & 7;
    if (e >= N_EDGES || f >= NCLASS) return;
    int s = src[e];
    int d = dst[e];
    float w = ew[e];
    atomicAdd(&out[d * NCLASS + f], g_support2[s * NCLASS + f] * w);
}

// ---------------- final: out = log_softmax(out + b2) ---------------------------
__global__ __launch_bounds__(256) void logsoftmax_kernel(const float* __restrict__ b2,
                                                         float* __restrict__ out) {
    int n = blockIdx.x * blockDim.x + threadIdx.x;
    if (n >= N_NODES) return;
    float v[NCLASS];
    float m = -1e30f;
#pragma unroll
    for (int c = 0; c < NCLASS; c++) {
        v[c] = out[n * NCLASS + c] + b2[c];
        m = fmaxf(m, v[c]);
    }
    float sum = 0.f;
#pragma unroll
    for (int c = 0; c < NCLASS; c++) sum += expf(v[c] - m);
    float l = m + logf(sum);
#pragma unroll
    for (int c = 0; c < NCLASS; c++) out[n * NCLASS + c] = v[c] - l;
}

// ---------------- launch --------------------------------------------------------
extern "C" void kernel_launch(void* const* d_in, const int* in_sizes, int n_in,
                              void* d_out, int out_size) {
    const float* x    = (const float*)d_in[0];
    const int*   src  = (const int*)d_in[1];
    const int*   dst  = (const int*)d_in[2];
    const float* ew   = (const float*)d_in[3];
    const float* W1   = (const float*)d_in[4];
    const float* b1   = (const float*)d_in[5];
    const float* W2   = (const float*)d_in[6];
    const float* b2   = (const float*)d_in[7];
    const float* mask = (const float*)d_in[8];
    float* out = (float*)d_out;

    (void)in_sizes; (void)n_in; (void)out_size;

    // zero scatter targets
    zero_agg1_kernel<<<(N_NODES * NHID / 4 + 255) / 256, 256>>>();
    zero_out_kernel<<<(N_NODES * NCLASS + 255) / 256, 256>>>(out);

    // layer 1 dense
    gemm1_kernel<<<(N_NODES + 127) / 128, 128>>>(x, W1);

    // layer 1 sparse aggregate (warp per edge)
    {
        long long total = (long long)N_EDGES * 32;
        int blocks = (int)((total + 255) / 256);
        scatter1_kernel<<<blocks, 256>>>(src, dst, ew);
    }

    // relu + bias + dropout + GEMM2 fused
    mid_kernel<<<(N_NODES + 255) / 256, 256>>>(b1, W2, mask);

    // layer 2 sparse aggregate
    {
        long long total = (long long)N_EDGES * 8;
        int blocks = (int)((total + 255) / 256);
        scatter2_kernel<<<blocks, 256>>>(src, dst, ew, out);
    }

    // bias + log_softmax
    logsoftmax_kernel<<<(N_NODES + 255) / 256, 256>>>(b2, out);
}

// round 3
// speedup vs baseline: 1.6157x; 1.6157x over previous
#include <cuda_runtime.h>
#include <cuda_bf16.h>

#define N_NODES 100000
#define N_EDGES 3200000
#define NFEAT 1433
#define NHID 40
#define NCLASS 7
#define NC_PAD 8   // padded class dim for vectorized reds

// ---------------- scratch (device globals; no allocations allowed) -------------
__device__ __align__(16) float g_support1[N_NODES * NHID];   // x @ W1
__device__ __align__(16) float g_agg1[N_NODES * NHID];       // scatter target 1
__device__ __align__(16) float g_support2[N_NODES * NC_PAD]; // h @ W2 (padded)
__device__ __align__(16) float g_agg2[N_NODES * NC_PAD];     // scatter target 2

// ---------------- f32x2 helpers (sm_100+ packed fp32) -------------------------
__device__ __forceinline__ unsigned long long pack_f32x2(float x) {
    unsigned long long p;
    asm("mov.b64 %0, {%1, %1};" : "=l"(p) : "f"(x));
    return p;
}
__device__ __forceinline__ void ffma2(unsigned long long& d,
                                      unsigned long long a,
                                      unsigned long long b) {
    asm("fma.rn.f32x2 %0, %1, %2, %0;" : "+l"(d) : "l"(a), "l"(b));
}
__device__ __forceinline__ float2 unpack_f32x2(unsigned long long p) {
    float2 r;
    asm("mov.b64 {%0, %1}, %2;" : "=f"(r.x), "=f"(r.y) : "l"(p));
    return r;
}

// vector fp32 reduction (sm_90+): one RED.128 instead of 4 scalar REDs
__device__ __forceinline__ void red_add_v4(float* addr, float4 v) {
    asm volatile("red.global.add.v4.f32 [%0], {%1, %2, %3, %4};"
                 :: "l"(addr), "f"(v.x), "f"(v.y), "f"(v.z), "f"(v.w)
                 : "memory");
}

// ---------------- GEMM1: support1 = x @ W1  (N x 1433 @ 1433 x 40) ------------
#define G1_KC 32
__global__ __launch_bounds__(128) void gemm1_kernel(const float* __restrict__ x,
                                                    const float* __restrict__ W1) {
    __shared__ float sx[128][G1_KC + 1];
    __shared__ float sw[G1_KC][NHID];

    const int tid = threadIdx.x;
    const int cg = tid & 3;
    const int rt = tid >> 2;
    const int row0 = blockIdx.x * 128;

    unsigned long long acc[4][5];
#pragma unroll
    for (int i = 0; i < 4; i++)
#pragma unroll
        for (int j = 0; j < 5; j++) acc[i][j] = 0ull;

    for (int kb = 0; kb < NFEAT; kb += G1_KC) {
#pragma unroll
        for (int i = 0; i < 32; i++) {
            int idx = tid + i * 128;
            int r = idx >> 5;
            int kk = idx & 31;
            int gr = row0 + r;
            int gk = kb + kk;
            float v = 0.f;
            if (gr < N_NODES && gk < NFEAT) v = x[gr * NFEAT + gk];
            sx[r][kk] = v;
        }
#pragma unroll
        for (int i = 0; i < 10; i++) {
            int idx = tid + i * 128;
            int kk = idx / NHID;
            int c = idx % NHID;
            int gk = kb + kk;
            sw[kk][c] = (gk < NFEAT) ? W1[gk * NHID + c] : 0.f;
        }
        __syncthreads();

#pragma unroll
        for (int kk = 0; kk < G1_KC; kk++) {
            unsigned long long wv[5];
            const float* wrow = &sw[kk][cg * 10];
#pragma unroll
            for (int j = 0; j < 5; j++)
                wv[j] = *reinterpret_cast<const unsigned long long*>(wrow + 2 * j);
#pragma unroll
            for (int i = 0; i < 4; i++) {
                unsigned long long xp = pack_f32x2(sx[rt * 4 + i][kk]);
#pragma unroll
                for (int j = 0; j < 5; j++) ffma2(acc[i][j], xp, wv[j]);
            }
        }
        __syncthreads();
    }

#pragma unroll
    for (int i = 0; i < 4; i++) {
        int gr = row0 + rt * 4 + i;
        if (gr < N_NODES) {
#pragma unroll
            for (int j = 0; j < 5; j++) {
                float2 v = unpack_f32x2(acc[i][j]);
                *reinterpret_cast<float2*>(&g_support1[gr * NHID + cg * 10 + 2 * j]) = v;
            }
        }
    }
}

// ---------------- zero both scatter targets ------------------------------------
__global__ void zero_kernel() {
    int i = blockIdx.x * blockDim.x + threadIdx.x;
    const int n1 = N_NODES * NHID / 4;
    const int n2 = N_NODES * NC_PAD / 4;
    if (i < n1)
        reinterpret_cast<float4*>(g_agg1)[i] = make_float4(0.f, 0.f, 0.f, 0.f);
    else if (i < n1 + n2)
        reinterpret_cast<float4*>(g_agg2)[i - n1] = make_float4(0.f, 0.f, 0.f, 0.f);
}

// ---------------- scatter 1: agg1[dst] += support1[src] * w  (40 wide) ---------
// Flat work: 10 v4-chunks per edge. One red.global.add.v4.f32 per chunk.
__global__ __launch_bounds__(256) void scatter1_kernel(const int* __restrict__ src,
                                                       const int* __restrict__ dst,
                                                       const float* __restrict__ ew) {
    int t = blockIdx.x * blockDim.x + threadIdx.x;
    if (t >= N_EDGES * 10) return;
    int e = t / 10;
    int c = t - e * 10;           // chunk 0..9
    int s = src[e];
    int d = dst[e];
    float w = ew[e];
    float4 v = reinterpret_cast<const float4*>(g_support1 + s * NHID)[c];
    v.x *= w; v.y *= w; v.z *= w; v.w *= w;
    red_add_v4(g_agg1 + d * NHID + c * 4, v);
}

// ---------------- layer-1 epilogue fused with GEMM2 ----------------------------
// h = relu(agg1 + b1) * dropout; support2 = h @ W2 (stride NC_PAD, slot 7 = 0)
__global__ __launch_bounds__(256) void mid_kernel(const float* __restrict__ b1,
                                                  const float* __restrict__ W2,
                                                  const float* __restrict__ mask) {
    __shared__ float sW2[NHID][NCLASS];
    __shared__ float sb1[NHID];
    int tid = threadIdx.x;
    for (int i = tid; i < NHID * NCLASS; i += blockDim.x)
        sW2[i / NCLASS][i % NCLASS] = W2[i];
    if (tid < NHID) sb1[tid] = b1[tid];
    __syncthreads();

    int n = blockIdx.x * blockDim.x + tid;
    if (n >= N_NODES) return;

    float acc[NC_PAD];
#pragma unroll
    for (int c = 0; c < NC_PAD; c++) acc[c] = 0.f;

    const float4* arow = reinterpret_cast<const float4*>(g_agg1 + n * NHID);
    const float4* mrow = reinterpret_cast<const float4*>(mask + n * NHID);
#pragma unroll
    for (int q = 0; q < NHID / 4; q++) {
        float4 a = arow[q];
        float4 m = mrow[q];
        float hv[4];
        hv[0] = (m.x > 0.5f) ? fmaxf(a.x + sb1[4 * q + 0], 0.f) * 2.f : 0.f;
        hv[1] = (m.y > 0.5f) ? fmaxf(a.y + sb1[4 * q + 1], 0.f) * 2.f : 0.f;
        hv[2] = (m.z > 0.5f) ? fmaxf(a.z + sb1[4 * q + 2], 0.f) * 2.f : 0.f;
        hv[3] = (m.w > 0.5f) ? fmaxf(a.w + sb1[4 * q + 3], 0.f) * 2.f : 0.f;
#pragma unroll
        for (int u = 0; u < 4; u++) {
#pragma unroll
            for (int c = 0; c < NCLASS; c++) acc[c] += hv[u] * sW2[4 * q + u][c];
        }
    }
    float4* orow = reinterpret_cast<float4*>(g_support2 + n * NC_PAD);
    orow[0] = make_float4(acc[0], acc[1], acc[2], acc[3]);
    orow[1] = make_float4(acc[4], acc[5], acc[6], 0.f);
}

// ---------------- scatter 2: agg2[dst] += support2[src] * w  (8 wide padded) ---
// 2 v4-chunks per edge.
__global__ __launch_bounds__(256) void scatter2_kernel(const int* __restrict__ src,
                                                       const int* __restrict__ dst,
                                                       const float* __restrict__ ew) {
    int t = blockIdx.x * blockDim.x + threadIdx.x;
    if (t >= N_EDGES * 2) return;
    int e = t >> 1;
    int c = t & 1;
    int s = src[e];
    int d = dst[e];
    float w = ew[e];
    float4 v = reinterpret_cast<const float4*>(g_support2 + s * NC_PAD)[c];
    v.x *= w; v.y *= w; v.z *= w; v.w *= w;
    red_add_v4(g_agg2 + d * NC_PAD + c * 4, v);
}

// ---------------- final: out = log_softmax(agg2 + b2) --------------------------
__global__ __launch_bounds__(256) void logsoftmax_kernel(const float* __restrict__ b2,
                                                         float* __restrict__ out) {
    int n = blockIdx.x * blockDim.x + threadIdx.x;
    if (n >= N_NODES) return;
    float v[NCLASS];
    float m = -1e30f;
#pragma unroll
    for (int c = 0; c < NCLASS; c++) {
        v[c] = g_agg2[n * NC_PAD + c] + b2[c];
        m = fmaxf(m, v[c]);
    }
    float sum = 0.f;
#pragma unroll
    for (int c = 0; c < NCLASS; c++) sum += expf(v[c] - m);
    float l = m + logf(sum);
#pragma unroll
    for (int c = 0; c < NCLASS; c++) out[n * NCLASS + c] = v[c] - l;
}

// ---------------- launch --------------------------------------------------------
extern "C" void kernel_launch(void* const* d_in, const int* in_sizes, int n_in,
                              void* d_out, int out_size) {
    const float* x    = (const float*)d_in[0];
    const int*   src  = (const int*)d_in[1];
    const int*   dst  = (const int*)d_in[2];
    const float* ew   = (const float*)d_in[3];
    const float* W1   = (const float*)d_in[4];
    const float* b1   = (const float*)d_in[5];
    const float* W2   = (const float*)d_in[6];
    const float* b2   = (const float*)d_in[7];
    const float* mask = (const float*)d_in[8];
    float* out = (float*)d_out;

    (void)in_sizes; (void)n_in; (void)out_size;

    // zero scatter targets (agg1 + agg2)
    {
        int total = N_NODES * NHID / 4 + N_NODES * NC_PAD / 4;
        zero_kernel<<<(total + 255) / 256, 256>>>();
    }

    // layer 1 dense
    gemm1_kernel<<<(N_NODES + 127) / 128, 128>>>(x, W1);

    // layer 1 sparse aggregate: 10 v4-chunks per edge
    {
        long long total = (long long)N_EDGES * 10;
        int blocks = (int)((total + 255) / 256);
        scatter1_kernel<<<blocks, 256>>>(src, dst, ew);
    }

    // relu + bias + dropout + GEMM2 fused
    mid_kernel<<<(N_NODES + 255) / 256, 256>>>(b1, W2, mask);

    // layer 2 sparse aggregate: 2 v4-chunks per edge
    {
        long long total = (long long)N_EDGES * 2;
        int blocks = (int)((total + 255) / 256);
        scatter2_kernel<<<blocks, 256>>>(src, dst, ew);
    }

    // bias + log_softmax (reads padded agg2, writes 7-wide out)
    logsoftmax_kernel<<<(N_NODES + 255) / 256, 256>>>(b2, out);
}